// round 7
// baseline (speedup 1.0000x reference)
#include <cuda_runtime.h>
#include <cstdint>
#include <math.h>

#define MAXG 1024
#define RESI 256
#define GSPLIT 32
#define GCHUNK 32    // MAXG / GSPLIT
#define NPB 64       // pixel blocks: 16 cols x 4 rowgroups (16w x 64h each)

__device__ float4   d_g0[MAXG];                        // mx, my, cA, cB
__device__ float4   d_g1[MAXG];                        // cC, log2(op), mask(punned), 0
__device__ float    d_partial[GSPLIT * RESI * RESI];   // 8 MB scratch
__device__ unsigned d_count[NPB];                      // zero-init; +GSPLIT per call per blk

__device__ __forceinline__ float ex2f(float x) {
    float y;
    asm("ex2.approx.ftz.f32 %0, %1;" : "=f"(y) : "f"(x));
    return y;
}

// ---------------------------------------------------------------------------
// Prep: one thread per gaussian -> conic coeffs (log2-domain) + tile bits.
// ---------------------------------------------------------------------------
__global__ void prep_kernel(const float* __restrict__ xyz,
                            const float* __restrict__ scaling,
                            const float* __restrict__ rotation,
                            const float* __restrict__ opacity,
                            const float* __restrict__ rot,
                            int N) {
    int i = blockIdx.x * blockDim.x + threadIdx.x;
    if (i >= N) return;
    const float RES = (float)RESI;

    float qr = rotation[4 * i + 0];
    float qx = rotation[4 * i + 1];
    float qy = rotation[4 * i + 2];
    float qz = rotation[4 * i + 3];
    float inv = rsqrtf(qr * qr + qx * qx + qy * qy + qz * qz);
    qr *= inv; qx *= inv; qy *= inv; qz *= inv;

    float R00 = 1.f - 2.f * (qy * qy + qz * qz);
    float R01 = 2.f * (qx * qy - qr * qz);
    float R02 = 2.f * (qx * qz + qr * qy);
    float R10 = 2.f * (qx * qy + qr * qz);
    float R11 = 1.f - 2.f * (qx * qx + qz * qz);
    float R12 = 2.f * (qy * qz - qr * qx);
    float R20 = 2.f * (qx * qz - qr * qy);
    float R21 = 2.f * (qy * qz + qr * qx);
    float R22 = 1.f - 2.f * (qx * qx + qy * qy);

    float sc0 = scaling[3 * i + 0];
    float sc1 = scaling[3 * i + 1];
    float sc2 = scaling[3 * i + 2];

    float L00 = R00 * sc0, L01 = R01 * sc1, L02 = R02 * sc2;
    float L10 = R10 * sc0, L11 = R11 * sc1, L12 = R12 * sc2;
    float L20 = R20 * sc0, L21 = R21 * sc1, L22 = R22 * sc2;

    float C00 = L00 * L00 + L01 * L01 + L02 * L02;
    float C01 = L00 * L10 + L01 * L11 + L02 * L12;
    float C02 = L00 * L20 + L01 * L21 + L02 * L22;
    float C11 = L10 * L10 + L11 * L11 + L12 * L12;
    float C12 = L10 * L20 + L11 * L21 + L12 * L22;
    float C22 = L20 * L20 + L21 * L21 + L22 * L22;

    float a00 = RES * rot[0], a01 = RES * rot[1], a02 = RES * rot[2];
    float a10 = RES * rot[3], a11 = RES * rot[4], a12 = RES * rot[5];

    float v0x = C00 * a00 + C01 * a01 + C02 * a02;
    float v0y = C01 * a00 + C11 * a01 + C12 * a02;
    float v0z = C02 * a00 + C12 * a01 + C22 * a02;
    float c00 = a00 * v0x + a01 * v0y + a02 * v0z;
    float c01 = a10 * v0x + a11 * v0y + a12 * v0z;
    float v1x = C00 * a10 + C01 * a11 + C02 * a12;
    float v1y = C01 * a10 + C11 * a11 + C12 * a12;
    float v1z = C02 * a10 + C12 * a11 + C22 * a12;
    float c11 = a10 * v1x + a11 * v1y + a12 * v1z;

    float det = c00 * c11 - c01 * c01;
    float mid = 0.5f * (c00 + c11);
    float sq = sqrtf(fmaxf(mid * mid - det, 0.1f));
    float lam = fmaxf(mid + sq, mid - sq);
    float radii = ceilf(3.0f * sqrtf(lam));

    float mx = xyz[3 * i + 0] * (RES * 0.5f);
    float my = xyz[3 * i + 1] * (RES * 0.5f);

    float rminx = fminf(fmaxf(mx - radii, 0.f), RES - 1.f);
    float rmaxx = fminf(fmaxf(mx + radii, 0.f), RES - 1.f);
    float rminy = fminf(fmaxf(my - radii, 0.f), RES - 1.f);
    float rmaxy = fminf(fmaxf(my + radii, 0.f), RES - 1.f);

    unsigned mw = 0u;
    #pragma unroll
    for (int tt = 0; tt < 16; tt++) {
        float ts = (float)(tt * 16);
        if (fminf(rmaxx, ts + 15.f) > fmaxf(rminx, ts)) mw |= (1u << tt);
        if (fminf(rmaxy, ts + 15.f) > fmaxf(rminy, ts)) mw |= (1u << (16 + tt));
    }

    float idet = 1.0f / det;
    const float L2E = 1.4426950408889634f;
    float cA = -0.5f * L2E * (c11 * idet);
    float cB = -0.5f * L2E * (c00 * idet);
    float cC = -0.5f * L2E * (-2.0f * c01 * idet);
    float lo = log2f(opacity[i]);          // fold opacity into exponent

    d_g0[i] = make_float4(mx, my, cA, cB);
    d_g1[i] = make_float4(cC, lo, __uint_as_float(mw), 0.f);
}

// ---------------------------------------------------------------------------
// Splat: CTA = 64 threads = 64 rows of a 16-wide column strip (4 stacked
// tiles), one GCHUNK=32 gaussian chunk. Each thread owns a FULL 16-px row.
//   q(k) = base + k*g + k^2*cA  ->  2 FFMA-imm + EX2 + FADD per pixel.
//   Per-row tile mask exactness via lo_eff = bit ? lo : -INF (ex2(-inf)=0).
// ---------------------------------------------------------------------------
__global__ void __launch_bounds__(64) splat_kernel(float* __restrict__ out, int N) {
    __shared__ float4 c0[GCHUNK];   // mx, my, cA, cB
    __shared__ float4 c1[GCHUNK];   // cC, lo, ymask4(punned), 0
    __shared__ int s_cnt;
    __shared__ unsigned s_old;

    int bid = blockIdx.x;
    int s   = bid & (GSPLIT - 1);   // gaussian split 0..31
    int blk = bid >> 5;             // pixel block 0..63
    int bx  = blk & 15;             // tile column
    int rg  = blk >> 4;             // row group 0..3 (64 rows each)

    int g0 = s * GCHUNK;
    int gN = N - g0;
    if (gN > GCHUNK) gN = GCHUNK;
    if (gN < 0) gN = 0;

    int t = threadIdx.x;            // 0..63 = row within group

    // ---- Phase 1: load + union-mask test + compact (warp 0 only) ----
    if (t < 32) {
        float4 q0 = make_float4(0.f, 0.f, 0.f, 0.f);
        float4 q1n = make_float4(0.f, 0.f, 0.f, 0.f);
        bool pass = false;
        if (t < gN) {
            q0 = d_g0[g0 + t];
            float4 q1 = d_g1[g0 + t];
            unsigned mw = __float_as_uint(q1.z);
            unsigned ym4 = (mw >> (16 + rg * 4)) & 0xFu;  // 4 y-tiles of this group
            pass = (((mw >> bx) & 1u) != 0u) && (ym4 != 0u);
            q1n = make_float4(q1.x, q1.y, __uint_as_float(ym4), 0.f);
        }
        unsigned bal = __ballot_sync(0xffffffffu, pass);
        int within = __popc(bal & ((1u << t) - 1u));
        if (pass) { c0[within] = q0; c1[within] = q1n; }
        if (t == 0) s_cnt = __popc(bal);
    }
    __syncthreads();
    int cnt = s_cnt;

    int y  = rg * 64 + t;
    int x0 = bx * 16;
    float px = (float)x0 - 127.5f;
    float py = (float)y  - 127.5f;
    unsigned tb = 1u << (t >> 4);   // my tile bit within the 4-group

    float acc[16];
    #pragma unroll
    for (int k = 0; k < 16; k++) acc[k] = 0.f;

    for (int i = 0; i < cnt; i++) {
        float4 q0 = c0[i];
        float4 q1 = c1[i];
        float dx = px - q0.x;
        float dy = py - q0.y;
        float cA = q0.z;
        float h  = q1.x * dy;                       // cC*dy
        float sB = q0.w * (dy * dy);                // cB*dy^2
        float inner = fmaf(cA, dx, h);
        float g  = fmaf(cA, dx + dx, h);            // dq/dk at k=0
        float lo = (__float_as_uint(q1.z) & tb) ? q1.y : -INFINITY;
        float base = fmaf(dx, inner, sB) + lo;      // q(0) + log2(op)

        #pragma unroll
        for (int k = 0; k < 16; k++) {
            float kf = (float)k;
            float qk = fmaf(kf * kf, cA, fmaf(kf, g, base));
            acc[k] += ex2f(qk);
        }
    }

    // ---- store partial (row of 16 = 4x float4) ----
    float* pp = &d_partial[s * (RESI * RESI) + y * RESI + x0];
    #pragma unroll
    for (int j = 0; j < 4; j++)
        reinterpret_cast<float4*>(pp)[j] =
            make_float4(acc[4 * j], acc[4 * j + 1], acc[4 * j + 2], acc[4 * j + 3]);

    // ---- Phase 3: last-CTA-per-block reduction (deterministic order) ----
    __threadfence();
    __syncthreads();
    if (t == 0) s_old = atomicAdd(&d_count[blk], 1u);
    __syncthreads();

    if (((s_old + 1) & (GSPLIT - 1)) == 0) {
        int rowoff = y * RESI + x0;
        float4 r0 = make_float4(0.f, 0.f, 0.f, 0.f);
        float4 r1 = r0, r2 = r0, r3 = r0;
        #pragma unroll 4
        for (int ss = 0; ss < GSPLIT; ss++) {
            const float4* p = reinterpret_cast<const float4*>(
                &d_partial[ss * (RESI * RESI) + rowoff]);
            float4 b0 = __ldcg(&p[0]);
            float4 b1 = __ldcg(&p[1]);
            float4 b2 = __ldcg(&p[2]);
            float4 b3 = __ldcg(&p[3]);
            r0.x += b0.x; r0.y += b0.y; r0.z += b0.z; r0.w += b0.w;
            r1.x += b1.x; r1.y += b1.y; r1.z += b1.z; r1.w += b1.w;
            r2.x += b2.x; r2.y += b2.y; r2.z += b2.z; r2.w += b2.w;
            r3.x += b3.x; r3.y += b3.y; r3.z += b3.z; r3.w += b3.w;
        }
        float4* po = reinterpret_cast<float4*>(&out[rowoff]);
        po[0] = r0; po[1] = r1; po[2] = r2; po[3] = r3;
    }
}

// ---------------------------------------------------------------------------
extern "C" void kernel_launch(void* const* d_in, const int* in_sizes, int n_in,
                              void* d_out, int out_size) {
    const float* xyz      = (const float*)d_in[0];
    const float* scaling  = (const float*)d_in[1];
    const float* rotation = (const float*)d_in[2];
    const float* opacity  = (const float*)d_in[3];
    const float* rot      = (const float*)d_in[4];

    int N = in_sizes[0] / 3;
    if (N > MAXG) N = MAXG;

    prep_kernel<<<(N + 127) / 128, 128>>>(xyz, scaling, rotation, opacity, rot, N);
    splat_kernel<<<NPB * GSPLIT, 64>>>((float*)d_out, N);
}

// round 9
// speedup vs baseline: 1.7315x; 1.7315x over previous
#include <cuda_runtime.h>
#include <cstdint>
#include <math.h>

#define MAXG 1024
#define RESI 256
#define GSPLIT 32
#define GCHUNK 32    // MAXG / GSPLIT
#define NPB 128      // pixel blocks: 16 tile-cols x 8 rowgroups (16w x 32h each)

__device__ float4   d_g0[MAXG];                        // mx, my, cA, cB
__device__ float4   d_g1[MAXG];                        // cC, log2(op), mask(punned), 0
__device__ float    d_partial[GSPLIT * RESI * RESI];   // 8 MB scratch
__device__ unsigned d_count[NPB];                      // zero-init; +GSPLIT per call per blk

__device__ __forceinline__ float ex2f(float x) {
    float y;
    asm("ex2.approx.ftz.f32 %0, %1;" : "=f"(y) : "f"(x));
    return y;
}

// ---------------------------------------------------------------------------
// Prep: one thread per gaussian -> conic coeffs (log2-domain) + tile bits.
// ---------------------------------------------------------------------------
__global__ void prep_kernel(const float* __restrict__ xyz,
                            const float* __restrict__ scaling,
                            const float* __restrict__ rotation,
                            const float* __restrict__ opacity,
                            const float* __restrict__ rot,
                            int N) {
    int i = blockIdx.x * blockDim.x + threadIdx.x;
    if (i >= N) return;
    const float RES = (float)RESI;

    float qr = rotation[4 * i + 0];
    float qx = rotation[4 * i + 1];
    float qy = rotation[4 * i + 2];
    float qz = rotation[4 * i + 3];
    float inv = rsqrtf(qr * qr + qx * qx + qy * qy + qz * qz);
    qr *= inv; qx *= inv; qy *= inv; qz *= inv;

    float R00 = 1.f - 2.f * (qy * qy + qz * qz);
    float R01 = 2.f * (qx * qy - qr * qz);
    float R02 = 2.f * (qx * qz + qr * qy);
    float R10 = 2.f * (qx * qy + qr * qz);
    float R11 = 1.f - 2.f * (qx * qx + qz * qz);
    float R12 = 2.f * (qy * qz - qr * qx);
    float R20 = 2.f * (qx * qz - qr * qy);
    float R21 = 2.f * (qy * qz + qr * qx);
    float R22 = 1.f - 2.f * (qx * qx + qy * qy);

    float sc0 = scaling[3 * i + 0];
    float sc1 = scaling[3 * i + 1];
    float sc2 = scaling[3 * i + 2];

    float L00 = R00 * sc0, L01 = R01 * sc1, L02 = R02 * sc2;
    float L10 = R10 * sc0, L11 = R11 * sc1, L12 = R12 * sc2;
    float L20 = R20 * sc0, L21 = R21 * sc1, L22 = R22 * sc2;

    float C00 = L00 * L00 + L01 * L01 + L02 * L02;
    float C01 = L00 * L10 + L01 * L11 + L02 * L12;
    float C02 = L00 * L20 + L01 * L21 + L02 * L22;
    float C11 = L10 * L10 + L11 * L11 + L12 * L12;
    float C12 = L10 * L20 + L11 * L21 + L12 * L22;
    float C22 = L20 * L20 + L21 * L21 + L22 * L22;

    float a00 = RES * rot[0], a01 = RES * rot[1], a02 = RES * rot[2];
    float a10 = RES * rot[3], a11 = RES * rot[4], a12 = RES * rot[5];

    float v0x = C00 * a00 + C01 * a01 + C02 * a02;
    float v0y = C01 * a00 + C11 * a01 + C12 * a02;
    float v0z = C02 * a00 + C12 * a01 + C22 * a02;
    float c00 = a00 * v0x + a01 * v0y + a02 * v0z;
    float c01 = a10 * v0x + a11 * v0y + a12 * v0z;
    float v1x = C00 * a10 + C01 * a11 + C02 * a12;
    float v1y = C01 * a10 + C11 * a11 + C12 * a12;
    float v1z = C02 * a10 + C12 * a11 + C22 * a12;
    float c11 = a10 * v1x + a11 * v1y + a12 * v1z;

    float det = c00 * c11 - c01 * c01;
    float mid = 0.5f * (c00 + c11);
    float sq = sqrtf(fmaxf(mid * mid - det, 0.1f));
    float lam = fmaxf(mid + sq, mid - sq);
    float radii = ceilf(3.0f * sqrtf(lam));

    float mx = xyz[3 * i + 0] * (RES * 0.5f);
    float my = xyz[3 * i + 1] * (RES * 0.5f);

    float rminx = fminf(fmaxf(mx - radii, 0.f), RES - 1.f);
    float rmaxx = fminf(fmaxf(mx + radii, 0.f), RES - 1.f);
    float rminy = fminf(fmaxf(my - radii, 0.f), RES - 1.f);
    float rmaxy = fminf(fmaxf(my + radii, 0.f), RES - 1.f);

    unsigned mw = 0u;
    #pragma unroll
    for (int tt = 0; tt < 16; tt++) {
        float ts = (float)(tt * 16);
        if (fminf(rmaxx, ts + 15.f) > fmaxf(rminx, ts)) mw |= (1u << tt);
        if (fminf(rmaxy, ts + 15.f) > fmaxf(rminy, ts)) mw |= (1u << (16 + tt));
    }

    float idet = 1.0f / det;
    const float L2E = 1.4426950408889634f;
    float cA = -0.5f * L2E * (c11 * idet);
    float cB = -0.5f * L2E * (c00 * idet);
    float cC = -0.5f * L2E * (-2.0f * c01 * idet);
    float lo = log2f(opacity[i]);          // fold opacity into exponent

    d_g0[i] = make_float4(mx, my, cA, cB);
    d_g1[i] = make_float4(cC, lo, __uint_as_float(mw), 0.f);
}

// ---------------------------------------------------------------------------
// Splat: CTA = 64 threads covering 16(w) x 32(h) px (one tile column, two
// stacked y-tiles), one GCHUNK=32 gaussian chunk. Each thread owns 8
// contiguous px of one row: row = t>>1, half = t&1.
//   q(k) = base + k*g + k^2*cA  ->  2 FFMA-imm + EX2 + FADD per pixel.
//   Y-tile exactness via lo = bit ? log2(op) : -INF (ex2(-inf)=0),
//   warp-uniform (warp id == y-tile within the pair).
// ---------------------------------------------------------------------------
__global__ void __launch_bounds__(64, 24) splat_kernel(float* __restrict__ out, int N) {
    __shared__ float4 c0[GCHUNK];   // mx, my, cA, cB
    __shared__ float4 c1[GCHUNK];   // cC, lo, ym2(punned), 0
    __shared__ int s_cnt;
    __shared__ unsigned s_old;

    int bid = blockIdx.x;
    int s   = bid & (GSPLIT - 1);   // gaussian split 0..31
    int blk = bid >> 5;             // pixel block 0..127
    int bx  = blk & 15;             // tile column
    int rg  = blk >> 4;             // row group 0..7 (32 rows each)

    int g0 = s * GCHUNK;
    int gN = N - g0;
    if (gN > GCHUNK) gN = GCHUNK;
    if (gN < 0) gN = 0;

    int t = threadIdx.x;            // 0..63

    // ---- Phase 1: load + mask test + compact (warp 0 only) ----
    if (t < 32) {
        float4 q0 = make_float4(0.f, 0.f, 0.f, 0.f);
        float4 q1n = make_float4(0.f, 0.f, 0.f, 0.f);
        bool pass = false;
        if (t < gN) {
            q0 = d_g0[g0 + t];
            float4 q1 = d_g1[g0 + t];
            unsigned mw = __float_as_uint(q1.z);
            unsigned ym2 = (mw >> (16 + rg * 2)) & 0x3u;  // 2 y-tiles of this group
            pass = (((mw >> bx) & 1u) != 0u) && (ym2 != 0u);
            q1n = make_float4(q1.x, q1.y, __uint_as_float(ym2), 0.f);
        }
        unsigned bal = __ballot_sync(0xffffffffu, pass);
        int within = __popc(bal & ((1u << t) - 1u));
        if (pass) { c0[within] = q0; c1[within] = q1n; }
        if (t == 0) s_cnt = __popc(bal);
    }
    __syncthreads();
    int cnt = s_cnt;

    int row  = t >> 1;              // 0..31
    int half = t & 1;               // 0 or 1
    int y  = rg * 32 + row;
    int x0 = bx * 16 + half * 8;
    float px = (float)x0 - 127.5f;
    float py = (float)y  - 127.5f;
    unsigned tb = 1u << (row >> 4); // my y-tile bit (warp-uniform: == warp id)

    float a0 = 0.f, a1 = 0.f, a2 = 0.f, a3 = 0.f;
    float a4 = 0.f, a5 = 0.f, a6 = 0.f, a7 = 0.f;

    #pragma unroll 2
    for (int i = 0; i < cnt; i++) {
        float4 q0 = c0[i];
        float4 q1 = c1[i];
        float dx = px - q0.x;
        float dy = py - q0.y;
        float cA = q0.z;
        float h  = q1.x * dy;                       // cC*dy
        float sB = q0.w * (dy * dy);                // cB*dy^2
        float inner = fmaf(cA, dx, h);
        float g  = fmaf(cA, dx + dx, h);            // linear coeff of q(k)-k^2*cA
        float lo = (__float_as_uint(q1.z) & tb) ? q1.y : -INFINITY;
        float base = fmaf(dx, inner, sB) + lo;      // q(0) + log2(op)

        a0 += ex2f(base);
        a1 += ex2f(fmaf(1.f,  cA, fmaf(1.f, g, base)));
        a2 += ex2f(fmaf(4.f,  cA, fmaf(2.f, g, base)));
        a3 += ex2f(fmaf(9.f,  cA, fmaf(3.f, g, base)));
        a4 += ex2f(fmaf(16.f, cA, fmaf(4.f, g, base)));
        a5 += ex2f(fmaf(25.f, cA, fmaf(5.f, g, base)));
        a6 += ex2f(fmaf(36.f, cA, fmaf(6.f, g, base)));
        a7 += ex2f(fmaf(49.f, cA, fmaf(7.f, g, base)));
    }

    // ---- store partial (8 floats = 2x float4) ----
    float* pp = &d_partial[s * (RESI * RESI) + y * RESI + x0];
    reinterpret_cast<float4*>(pp)[0] = make_float4(a0, a1, a2, a3);
    reinterpret_cast<float4*>(pp)[1] = make_float4(a4, a5, a6, a7);

    // ---- Phase 3: last-CTA-per-block reduction (deterministic order) ----
    __threadfence();
    __syncthreads();
    if (t == 0) s_old = atomicAdd(&d_count[blk], 1u);
    __syncthreads();

    if (((s_old + 1) & (GSPLIT - 1)) == 0) {
        int rowoff = y * RESI + x0;
        float4 r0 = make_float4(0.f, 0.f, 0.f, 0.f);
        float4 r1 = r0;
        #pragma unroll 4
        for (int ss = 0; ss < GSPLIT; ss++) {
            const float4* p = reinterpret_cast<const float4*>(
                &d_partial[ss * (RESI * RESI) + rowoff]);
            float4 b0 = __ldcg(&p[0]);
            float4 b1 = __ldcg(&p[1]);
            r0.x += b0.x; r0.y += b0.y; r0.z += b0.z; r0.w += b0.w;
            r1.x += b1.x; r1.y += b1.y; r1.z += b1.z; r1.w += b1.w;
        }
        float4* po = reinterpret_cast<float4*>(&out[rowoff]);
        po[0] = r0; po[1] = r1;
    }
}

// ---------------------------------------------------------------------------
extern "C" void kernel_launch(void* const* d_in, const int* in_sizes, int n_in,
                              void* d_out, int out_size) {
    const float* xyz      = (const float*)d_in[0];
    const float* scaling  = (const float*)d_in[1];
    const float* rotation = (const float*)d_in[2];
    const float* opacity  = (const float*)d_in[3];
    const float* rot      = (const float*)d_in[4];

    int N = in_sizes[0] / 3;
    if (N > MAXG) N = MAXG;

    prep_kernel<<<(N + 127) / 128, 128>>>(xyz, scaling, rotation, opacity, rot, N);
    splat_kernel<<<NPB * GSPLIT, 64>>>((float*)d_out, N);
}

// round 11
// speedup vs baseline: 2.6703x; 1.5422x over previous
#include <cuda_runtime.h>
#include <cstdint>

#define MAXG 1024
#define RESI 256
#define GSPLIT 16
#define GCHUNK 64    // MAXG / GSPLIT
#define NTILE 256    // 16x16 tiles

__device__ float4   d_g0[MAXG];                        // mx, my, cA, cB
__device__ float4   d_g1[MAXG];                        // cC, opacity, mask(punned), 0
__device__ float    d_partial[GSPLIT * RESI * RESI];   // 4 MB scratch
__device__ unsigned d_count[NTILE];                    // zero-init; +GSPLIT per call per tile

__device__ __forceinline__ float ex2f(float x) {
    float y;
    asm("ex2.approx.ftz.f32 %0, %1;" : "=f"(y) : "f"(x));
    return y;
}

// ---------------------------------------------------------------------------
// Prep: one thread per gaussian -> conic coeffs + 16+16 tile-interval bits.
// ---------------------------------------------------------------------------
__global__ void prep_kernel(const float* __restrict__ xyz,
                            const float* __restrict__ scaling,
                            const float* __restrict__ rotation,
                            const float* __restrict__ opacity,
                            const float* __restrict__ rot,
                            int N) {
    int i = blockIdx.x * blockDim.x + threadIdx.x;
    if (i >= N) return;
    const float RES = (float)RESI;

    float qr = rotation[4 * i + 0];
    float qx = rotation[4 * i + 1];
    float qy = rotation[4 * i + 2];
    float qz = rotation[4 * i + 3];
    float inv = rsqrtf(qr * qr + qx * qx + qy * qy + qz * qz);
    qr *= inv; qx *= inv; qy *= inv; qz *= inv;

    float R00 = 1.f - 2.f * (qy * qy + qz * qz);
    float R01 = 2.f * (qx * qy - qr * qz);
    float R02 = 2.f * (qx * qz + qr * qy);
    float R10 = 2.f * (qx * qy + qr * qz);
    float R11 = 1.f - 2.f * (qx * qx + qz * qz);
    float R12 = 2.f * (qy * qz - qr * qx);
    float R20 = 2.f * (qx * qz - qr * qy);
    float R21 = 2.f * (qy * qz + qr * qx);
    float R22 = 1.f - 2.f * (qx * qx + qy * qy);

    float sc0 = scaling[3 * i + 0];
    float sc1 = scaling[3 * i + 1];
    float sc2 = scaling[3 * i + 2];

    float L00 = R00 * sc0, L01 = R01 * sc1, L02 = R02 * sc2;
    float L10 = R10 * sc0, L11 = R11 * sc1, L12 = R12 * sc2;
    float L20 = R20 * sc0, L21 = R21 * sc1, L22 = R22 * sc2;

    float C00 = L00 * L00 + L01 * L01 + L02 * L02;
    float C01 = L00 * L10 + L01 * L11 + L02 * L12;
    float C02 = L00 * L20 + L01 * L21 + L02 * L22;
    float C11 = L10 * L10 + L11 * L11 + L12 * L12;
    float C12 = L10 * L20 + L11 * L21 + L12 * L22;
    float C22 = L20 * L20 + L21 * L21 + L22 * L22;

    float a00 = RES * rot[0], a01 = RES * rot[1], a02 = RES * rot[2];
    float a10 = RES * rot[3], a11 = RES * rot[4], a12 = RES * rot[5];

    float v0x = C00 * a00 + C01 * a01 + C02 * a02;
    float v0y = C01 * a00 + C11 * a01 + C12 * a02;
    float v0z = C02 * a00 + C12 * a01 + C22 * a02;
    float c00 = a00 * v0x + a01 * v0y + a02 * v0z;
    float c01 = a10 * v0x + a11 * v0y + a12 * v0z;
    float v1x = C00 * a10 + C01 * a11 + C02 * a12;
    float v1y = C01 * a10 + C11 * a11 + C12 * a12;
    float v1z = C02 * a10 + C12 * a11 + C22 * a12;
    float c11 = a10 * v1x + a11 * v1y + a12 * v1z;

    float det = c00 * c11 - c01 * c01;
    float mid = 0.5f * (c00 + c11);
    float sq = sqrtf(fmaxf(mid * mid - det, 0.1f));
    float lam = fmaxf(mid + sq, mid - sq);
    float radii = ceilf(3.0f * sqrtf(lam));

    float mx = xyz[3 * i + 0] * (RES * 0.5f);
    float my = xyz[3 * i + 1] * (RES * 0.5f);

    float rminx = fminf(fmaxf(mx - radii, 0.f), RES - 1.f);
    float rmaxx = fminf(fmaxf(mx + radii, 0.f), RES - 1.f);
    float rminy = fminf(fmaxf(my - radii, 0.f), RES - 1.f);
    float rmaxy = fminf(fmaxf(my + radii, 0.f), RES - 1.f);

    unsigned mw = 0u;
    #pragma unroll
    for (int tt = 0; tt < 16; tt++) {
        float ts = (float)(tt * 16);
        if (fminf(rmaxx, ts + 15.f) > fmaxf(rminx, ts)) mw |= (1u << tt);
        if (fminf(rmaxy, ts + 15.f) > fmaxf(rminy, ts)) mw |= (1u << (16 + tt));
    }

    float idet = 1.0f / det;
    const float L2E = 1.4426950408889634f;
    float cA = -0.5f * L2E * (c11 * idet);
    float cB = -0.5f * L2E * (c00 * idet);
    float cC = -0.5f * L2E * (-2.0f * c01 * idet);

    d_g0[i] = make_float4(mx, my, cA, cB);
    d_g1[i] = make_float4(cC, opacity[i], __uint_as_float(mw), 0.f);
}

// ---------------------------------------------------------------------------
// Splat: one CTA = one 16x16 tile x one 64-gaussian chunk, 64 threads.
// Identical to the best (R6) kernel except the inner loop uses the
// quadratic-in-k update: q(k) = base + k*g + k^2*cA (FFMA-imm forms).
// ---------------------------------------------------------------------------
__global__ void __launch_bounds__(64) splat_kernel(float* __restrict__ out, int N) {
    __shared__ float4 c0[GCHUNK];         // mx, my, cA, cB (compacted)
    __shared__ float2 c1[GCHUNK];         // cC, opacity    (compacted)
    __shared__ int    s_warpcnt[2];
    __shared__ unsigned s_old;

    int bid = blockIdx.x;
    int s   = bid & (GSPLIT - 1);   // gaussian split
    int blk = bid >> 4;             // tile 0..255
    int bx  = blk & 15;             // tile column
    int ty  = blk >> 4;             // tile row

    int g0 = s * GCHUNK;
    int gN = N - g0;
    if (gN > GCHUNK) gN = GCHUNK;
    if (gN < 0) gN = 0;

    int t    = threadIdx.x;         // 0..63
    int lane = t & 31;
    int wid  = t >> 5;

    // ---- Phase 1: load precomputed params + mask test + compact ----
    float4 q0v = make_float4(0.f, 0.f, 0.f, 0.f);
    float4 q1v = make_float4(0.f, 0.f, 0.f, 0.f);
    bool pass = false;
    if (t < gN) {
        q0v = d_g0[g0 + t];
        q1v = d_g1[g0 + t];
        unsigned mw = __float_as_uint(q1v.z);
        pass = ((mw >> bx) & (mw >> (16 + ty)) & 1u) != 0u;
    }

    unsigned bal = __ballot_sync(0xffffffffu, pass);
    int within = __popc(bal & ((1u << lane) - 1u));
    if (lane == 0) s_warpcnt[wid] = __popc(bal);
    __syncthreads();
    int base_off = (wid == 1) ? s_warpcnt[0] : 0;
    int cnt = s_warpcnt[0] + s_warpcnt[1];
    if (pass) {
        int p = base_off + within;
        c0[p] = q0v;
        c1[p] = make_float2(q1v.x, q1v.y);
    }
    __syncthreads();

    // ---- Phase 2: dense branch-free splat, 4 px per thread (one row) ----
    int cg  = t & 3;
    int row = t >> 2;               // 0..15
    int x = bx * 16 + cg * 4;
    int y = ty * 16 + row;

    float px = (float)x - 127.5f;
    float py = (float)y - 127.5f;

    float a0 = 0.f, a1 = 0.f, a2 = 0.f, a3 = 0.f;

    #pragma unroll 2
    for (int i = 0; i < cnt; i++) {
        float4 q0 = c0[i];
        float2 q1 = c1[i];
        float dx = px - q0.x;
        float dy = py - q0.y;
        float cAi = q0.z;
        float h  = q1.x * dy;               // cC * dy
        float sB = q0.w * (dy * dy);        // cB * dy^2
        float o  = q1.y;

        float inner = fmaf(cAi, dx, h);     // cA*dx + h
        float g     = fmaf(cAi, dx, inner); // 2*cA*dx + h  (linear coeff in k)
        float base  = fmaf(dx, inner, sB);  // q(0)

        float w0 = ex2f(base);
        float w1 = ex2f(fmaf(1.f, cAi, fmaf(1.f, g, base)));
        float w2 = ex2f(fmaf(4.f, cAi, fmaf(2.f, g, base)));
        float w3 = ex2f(fmaf(9.f, cAi, fmaf(3.f, g, base)));

        a0 = fmaf(w0, o, a0);
        a1 = fmaf(w1, o, a1);
        a2 = fmaf(w2, o, a2);
        a3 = fmaf(w3, o, a3);
    }

    int pix = y * RESI + x;
    *reinterpret_cast<float4*>(&d_partial[s * (RESI * RESI) + pix]) =
        make_float4(a0, a1, a2, a3);

    // ---- Phase 3: last-CTA-per-tile reduction (deterministic order) ----
    __threadfence();
    __syncthreads();
    if (t == 0) s_old = atomicAdd(&d_count[blk], 1u);
    __syncthreads();

    if (((s_old + 1) & (GSPLIT - 1)) == 0) {
        const float4* p = reinterpret_cast<const float4*>(d_partial);
        int idx = pix >> 2;
        float4 a = __ldcg(&p[idx]);
        #pragma unroll
        for (int ss = 1; ss < GSPLIT; ss++) {
            float4 b = __ldcg(&p[ss * (RESI * RESI / 4) + idx]);
            a.x += b.x; a.y += b.y; a.z += b.z; a.w += b.w;
        }
        *reinterpret_cast<float4*>(&out[pix]) = a;
    }
}

// ---------------------------------------------------------------------------
extern "C" void kernel_launch(void* const* d_in, const int* in_sizes, int n_in,
                              void* d_out, int out_size) {
    const float* xyz      = (const float*)d_in[0];
    const float* scaling  = (const float*)d_in[1];
    const float* rotation = (const float*)d_in[2];
    const float* opacity  = (const float*)d_in[3];
    const float* rot      = (const float*)d_in[4];

    int N = in_sizes[0] / 3;
    if (N > MAXG) N = MAXG;

    prep_kernel<<<(N + 127) / 128, 128>>>(xyz, scaling, rotation, opacity, rot, N);
    splat_kernel<<<NTILE * GSPLIT, 64>>>((float*)d_out, N);
}